// round 1
// baseline (speedup 1.0000x reference)
#include <cuda_runtime.h>
#include <cstdint>
#include <math.h>

#define NBINS 256
#define GHH 8
#define GWW 8
#define TILE_PIXELS 16384   // 128*128
#define MAXC 32

struct Params { float c1, c2, maxval; int flag; };

__device__ double   g_sum_d;
__device__ double   g_sumsq_d;
__device__ unsigned g_min_enc;
__device__ unsigned g_max_enc;
__device__ Params   g_par;
__device__ float    g_lut[MAXC * 64 * NBINS];          // 2 MB
__device__ float4   g_tbl[MAXC * 81 * NBINS];          // 10.6 MB  (p,q,r,s) per region/bin
__device__ unsigned g_bins[(MAXC << 20) >> 2];         // 32 MB packed u8 lookup bins

__device__ __forceinline__ unsigned fenc(float f) {
    unsigned u = __float_as_uint(f);
    return (u & 0x80000000u) ? ~u : (u | 0x80000000u);
}
__device__ __forceinline__ float fdec(unsigned e) {
    unsigned u = (e & 0x80000000u) ? (e & 0x7FFFFFFFu) : ~e;
    return __uint_as_float(u);
}

// ---------------------------------------------------------------- reset
__global__ void k_reset() {
    if (threadIdx.x == 0) {
        g_sum_d = 0.0; g_sumsq_d = 0.0;
        g_min_enc = 0xFFFFFFFFu; g_max_enc = 0u;
    }
}

// ---------------------------------------------------------------- reduce: sum, sumsq, min, max
__global__ void __launch_bounds__(256) k_reduce(const float4* __restrict__ x, int n16) {
    double s = 0.0, q = 0.0;
    float mn = 3.4e38f, mx = -3.4e38f;
    int stride = gridDim.x * blockDim.x;
    for (int i = blockIdx.x * blockDim.x + threadIdx.x; i < n16; i += stride) {
        const float4* p = x + (size_t)i * 4;
        float fs = 0.0f, fq = 0.0f;
#pragma unroll
        for (int g = 0; g < 4; g++) {
            float4 v = p[g];
            fs += v.x; fq = fmaf(v.x, v.x, fq); mn = fminf(mn, v.x); mx = fmaxf(mx, v.x);
            fs += v.y; fq = fmaf(v.y, v.y, fq); mn = fminf(mn, v.y); mx = fmaxf(mx, v.y);
            fs += v.z; fq = fmaf(v.z, v.z, fq); mn = fminf(mn, v.z); mx = fmaxf(mx, v.z);
            fs += v.w; fq = fmaf(v.w, v.w, fq); mn = fminf(mn, v.w); mx = fmaxf(mx, v.w);
        }
        s += (double)fs; q += (double)fq;
    }
#pragma unroll
    for (int o = 16; o; o >>= 1) {
        s  += __shfl_down_sync(0xffffffffu, s, o);
        q  += __shfl_down_sync(0xffffffffu, q, o);
        mn = fminf(mn, __shfl_down_sync(0xffffffffu, mn, o));
        mx = fmaxf(mx, __shfl_down_sync(0xffffffffu, mx, o));
    }
    __shared__ double ss[8], sq[8];
    __shared__ float  smn[8], smx[8];
    int w = threadIdx.x >> 5, l = threadIdx.x & 31;
    if (l == 0) { ss[w] = s; sq[w] = q; smn[w] = mn; smx[w] = mx; }
    __syncthreads();
    if (w == 0) {
        s  = (l < 8) ? ss[l]  : 0.0;
        q  = (l < 8) ? sq[l]  : 0.0;
        mn = (l < 8) ? smn[l] : 3.4e38f;
        mx = (l < 8) ? smx[l] : -3.4e38f;
#pragma unroll
        for (int o = 4; o; o >>= 1) {
            s  += __shfl_down_sync(0xffffffffu, s, o);
            q  += __shfl_down_sync(0xffffffffu, q, o);
            mn = fminf(mn, __shfl_down_sync(0xffffffffu, mn, o));
            mx = fmaxf(mx, __shfl_down_sync(0xffffffffu, mx, o));
        }
        if (l == 0) {
            atomicAdd(&g_sum_d, s);
            atomicAdd(&g_sumsq_d, q);
            atomicMin(&g_min_enc, fenc(mn));
            atomicMax(&g_max_enc, fenc(mx));
        }
    }
}

// ---------------------------------------------------------------- scalar stats
__global__ void k_stats(int n) {
    double s = g_sum_d, q = g_sumsq_d;
    double dn = (double)n;
    double var = (q - s * s / dn) / (dn - 1.0);
    double sd = sqrt(var);
    float xminf = fdec(g_min_enc), xmaxf = fdec(g_max_enc);
    double range = (double)xmaxf - (double)xminf;
    double ct = sd / range;                 // std(x01) == std(x)/range
    int flag = (ct < 0.05) ? 1 : 0;
    double beta = 10.0 * ct;
    double cl = 1.0 / (1.0 - beta) + beta;
    double mv = floor(cl * (double)TILE_PIXELS / (double)NBINS);
    if (mv < 1.0) mv = 1.0;
    Params p;
    p.c1 = (float)(1.0 / range);
    p.c2 = (float)(-(double)xminf / range);
    p.maxval = (float)mv;
    p.flag = flag;
    g_par = p;
}

// ---------------------------------------------------------------- per-tile histogram + LUT (fused)
__global__ void __launch_bounds__(256) k_hist_lut(const float4* __restrict__ x) {
    __shared__ unsigned sh[8][NBINS];
    __shared__ float red[40];
    Params p = g_par;
    if (!p.flag) return;
    int t = threadIdx.x;
    int bid = blockIdx.x;                 // tile id: c*64 + gy*8 + gx
    int c = bid >> 6, gy = (bid >> 3) & 7, gx = bid & 7;
#pragma unroll
    for (int k = 0; k < 8; k++) sh[k][t] = 0u;
    __syncthreads();

    int wid = t >> 5, lane = t & 31;
    unsigned lt_mask = (1u << lane) - 1u;
    float c1 = p.c1, c2 = p.c2;
    int base = c * 262144 + (gy * 128) * 256 + gx * 32;   // float4 index of tile origin

#pragma unroll 4
    for (int it = 0; it < 16; it++) {
        int f = it * 256 + t;             // 0..4095 float4s of this tile
        int row = f >> 5, col = f & 31;
        int gidx = base + row * 256 + col;
        float4 v = x[gidx];
        unsigned packed = 0u;
        float vals[4] = { v.x, v.y, v.z, v.w };
#pragma unroll
        for (int j = 0; j < 4; j++) {
            float x01 = fmaf(vals[j], c1, c2);
            int hb = (int)(x01 * 256.0f);          // trunc; tiny negatives -> 0
            hb = min(max(hb, 0), 255);
            int lb = (int)(x01 * 255.0f);
            lb = min(max(lb, 0), 255);
            packed |= ((unsigned)lb) << (8 * j);
            unsigned m = __match_any_sync(0xffffffffu, hb);
            if ((m & lt_mask) == 0u)               // lowest matching lane
                atomicAdd(&sh[wid][hb], (unsigned)__popc(m));
        }
        g_bins[gidx] = packed;
    }
    __syncthreads();

    // counts -> clip -> redistribute -> scan -> LUT   (all exact integer f32 math)
    unsigned cnt = 0;
#pragma unroll
    for (int k = 0; k < 8; k++) cnt += sh[k][t];
    float clipped = fminf((float)cnt, p.maxval);

    float s = clipped;
#pragma unroll
    for (int o = 16; o; o >>= 1) s += __shfl_down_sync(0xffffffffu, s, o);
    if (lane == 0) red[wid] = s;
    __syncthreads();
    if (t < 32) {
        float v2 = (t < 8) ? red[t] : 0.0f;
#pragma unroll
        for (int o = 4; o; o >>= 1) v2 += __shfl_down_sync(0xffffffffu, v2, o);
        if (t == 0) red[32] = v2;
    }
    __syncthreads();
    float total = red[32];
    int ex = TILE_PIXELS - (int)total;     // >= 0
    int residual = ex & (NBINS - 1);
    int redist = ex >> 8;
    float hv = clipped + (float)redist + ((t < residual) ? 1.0f : 0.0f);

    // inclusive block scan
    float vsc = hv;
#pragma unroll
    for (int o = 1; o < 32; o <<= 1) {
        float u = __shfl_up_sync(0xffffffffu, vsc, o);
        if (lane >= o) vsc += u;
    }
    if (lane == 31) red[wid] = vsc;
    __syncthreads();
    float off = 0.0f;
    for (int k = 0; k < wid; k++) off += red[k];
    vsc += off;

    float lutv = floorf(fminf(vsc * (255.0f / 16384.0f), 255.0f));
    g_lut[bid * NBINS + t] = lutv;
}

// ---------------------------------------------------------------- per-region prefactored bilinear table
__global__ void __launch_bounds__(256) k_tbl() {
    Params p = g_par;
    if (!p.flag) return;
    int t = threadIdx.x, b = blockIdx.x;       // b = c*81 + ry*9 + rx
    int c = b / 81, r = b % 81;
    int ry = r / 9, rx = r % 9;
    int y0 = max(ry - 1, 0); int y1 = min(y0 + 1, 7);
    int x0 = max(rx - 1, 0); int x1 = min(x0 + 1, 7);
    const float* L = g_lut + c * 64 * NBINS;
    float l00 = L[(y0 * 8 + x0) * NBINS + t];
    float l01 = L[(y0 * 8 + x1) * NBINS + t];
    float l10 = L[(y1 * 8 + x0) * NBINS + t];
    float l11 = L[(y1 * 8 + x1) * NBINS + t];
    float4 o;
    o.x = l00;
    o.y = l01 - l00;
    o.z = l10 - l00;
    o.w = l11 - l10 - l01 + l00;
    g_tbl[b * NBINS + t] = o;
}

// ---------------------------------------------------------------- output: gather + interp + log2
__global__ void __launch_bounds__(256) k_out(const float4* __restrict__ x,
                                             float4* __restrict__ out, int n4) {
    Params p = g_par;
    int stride = gridDim.x * blockDim.x;
    if (p.flag) {
        for (int i = blockIdx.x * blockDim.x + threadIdx.x; i < n4; i += stride) {
            int c   = i >> 18;
            int rem = i & 262143;
            int h   = rem >> 8;
            int w4  = (rem & 255) << 2;
            int ry  = (h + 64) >> 7;
            int rx  = (w4 + 64) >> 7;
            float wy  = fmaf((float)h,  0.0078125f, 0.50390625f - (float)ry);
            float wx0 = fmaf((float)w4, 0.0078125f, 0.50390625f - (float)rx);
            const float4* tb = g_tbl + (((c * 81) + ry * 9 + rx) << 8);
            unsigned bp = g_bins[i];
            float o[4];
#pragma unroll
            for (int j = 0; j < 4; j++) {
                float4 v = tb[(bp >> (8 * j)) & 255u];
                float wx = wx0 + (float)j * 0.0078125f;
                float itp = fmaf(wy, fmaf(wx, v.w, v.z), fmaf(wx, v.y, v.x));
                float val = itp * (1.0f / 255.0f);
                o[j] = log2f(1.0f + val);
            }
            float4 ov; ov.x = o[0]; ov.y = o[1]; ov.z = o[2]; ov.w = o[3];
            out[i] = ov;
        }
    } else {
        for (int i = blockIdx.x * blockDim.x + threadIdx.x; i < n4; i += stride) {
            float4 v = x[i];
            float4 ov;
            ov.x = log2f(1.0f + fmaf(v.x, p.c1, p.c2));
            ov.y = log2f(1.0f + fmaf(v.y, p.c1, p.c2));
            ov.z = log2f(1.0f + fmaf(v.z, p.c1, p.c2));
            ov.w = log2f(1.0f + fmaf(v.w, p.c1, p.c2));
            out[i] = ov;
        }
    }
}

// ---------------------------------------------------------------- launch
extern "C" void kernel_launch(void* const* d_in, const int* in_sizes, int n_in,
                              void* d_out, int out_size) {
    (void)n_in; (void)out_size;
    const float* x = (const float*)d_in[0];
    int n   = in_sizes[0];          // 32 * 1024 * 1024
    int C   = n >> 20;
    int n16 = n >> 4;
    int n4  = n >> 2;

    k_reset<<<1, 32>>>();
    k_reduce<<<1480, 256>>>((const float4*)x, n16);
    k_stats<<<1, 1>>>(n);
    k_hist_lut<<<C * 64, 256>>>((const float4*)x);
    k_tbl<<<C * 81, 256>>>();
    k_out<<<3552, 256>>>((const float4*)x, (float4*)d_out, n4);
}

// round 2
// speedup vs baseline: 1.1329x; 1.1329x over previous
#include <cuda_runtime.h>
#include <cstdint>
#include <math.h>

#define NBINS 256
#define TILE_PIXELS 16384   // 128*128
#define MAXC 32

struct Params { float c1, c2, maxval; int flag; };

__device__ double   g_sum_d;
__device__ double   g_sumsq_d;
__device__ unsigned g_min_enc;
__device__ unsigned g_max_enc;
__device__ Params   g_par;
__device__ float    g_lut[MAXC * 64 * NBINS];          // 2 MB
__device__ float4   g_tbl[MAXC * 81 * NBINS];          // 10.6 MB  (p,q,r,s) per region/bin
__device__ unsigned g_bins[(MAXC << 20) >> 2];         // 32 MB packed u8 lookup bins

__device__ __forceinline__ unsigned fenc(float f) {
    unsigned u = __float_as_uint(f);
    return (u & 0x80000000u) ? ~u : (u | 0x80000000u);
}
__device__ __forceinline__ float fdec(unsigned e) {
    unsigned u = (e & 0x80000000u) ? (e & 0x7FFFFFFFu) : ~e;
    return __uint_as_float(u);
}

// ---------------------------------------------------------------- reset
__global__ void k_reset() {
    if (threadIdx.x == 0) {
        g_sum_d = 0.0; g_sumsq_d = 0.0;
        g_min_enc = 0xFFFFFFFFu; g_max_enc = 0u;
    }
}

// ---------------------------------------------------------------- reduce: sum, sumsq, min, max
__global__ void __launch_bounds__(256) k_reduce(const float4* __restrict__ x, int n16) {
    double s = 0.0, q = 0.0;
    float mn = 3.4e38f, mx = -3.4e38f;
    int stride = gridDim.x * blockDim.x;
    for (int i = blockIdx.x * blockDim.x + threadIdx.x; i < n16; i += stride) {
        const float4* p = x + (size_t)i * 4;
        float fs = 0.0f, fq = 0.0f;
#pragma unroll
        for (int g = 0; g < 4; g++) {
            float4 v = p[g];
            fs += v.x; fq = fmaf(v.x, v.x, fq); mn = fminf(mn, v.x); mx = fmaxf(mx, v.x);
            fs += v.y; fq = fmaf(v.y, v.y, fq); mn = fminf(mn, v.y); mx = fmaxf(mx, v.y);
            fs += v.z; fq = fmaf(v.z, v.z, fq); mn = fminf(mn, v.z); mx = fmaxf(mx, v.z);
            fs += v.w; fq = fmaf(v.w, v.w, fq); mn = fminf(mn, v.w); mx = fmaxf(mx, v.w);
        }
        s += (double)fs; q += (double)fq;
    }
#pragma unroll
    for (int o = 16; o; o >>= 1) {
        s  += __shfl_down_sync(0xffffffffu, s, o);
        q  += __shfl_down_sync(0xffffffffu, q, o);
        mn = fminf(mn, __shfl_down_sync(0xffffffffu, mn, o));
        mx = fmaxf(mx, __shfl_down_sync(0xffffffffu, mx, o));
    }
    __shared__ double ss[8], sq[8];
    __shared__ float  smn[8], smx[8];
    int w = threadIdx.x >> 5, l = threadIdx.x & 31;
    if (l == 0) { ss[w] = s; sq[w] = q; smn[w] = mn; smx[w] = mx; }
    __syncthreads();
    if (w == 0) {
        s  = (l < 8) ? ss[l]  : 0.0;
        q  = (l < 8) ? sq[l]  : 0.0;
        mn = (l < 8) ? smn[l] : 3.4e38f;
        mx = (l < 8) ? smx[l] : -3.4e38f;
#pragma unroll
        for (int o = 4; o; o >>= 1) {
            s  += __shfl_down_sync(0xffffffffu, s, o);
            q  += __shfl_down_sync(0xffffffffu, q, o);
            mn = fminf(mn, __shfl_down_sync(0xffffffffu, mn, o));
            mx = fmaxf(mx, __shfl_down_sync(0xffffffffu, mx, o));
        }
        if (l == 0) {
            atomicAdd(&g_sum_d, s);
            atomicAdd(&g_sumsq_d, q);
            atomicMin(&g_min_enc, fenc(mn));
            atomicMax(&g_max_enc, fenc(mx));
        }
    }
}

// ---------------------------------------------------------------- scalar stats
__global__ void k_stats(int n) {
    double s = g_sum_d, q = g_sumsq_d;
    double dn = (double)n;
    double var = (q - s * s / dn) / (dn - 1.0);
    double sd = sqrt(var);
    float xminf = fdec(g_min_enc), xmaxf = fdec(g_max_enc);
    double range = (double)xmaxf - (double)xminf;
    double ct = sd / range;                 // std(x01) == std(x)/range
    int flag = (ct < 0.05) ? 1 : 0;
    double beta = 10.0 * ct;
    double cl = 1.0 / (1.0 - beta) + beta;
    double mv = floor(cl * (double)TILE_PIXELS / (double)NBINS);
    if (mv < 1.0) mv = 1.0;
    Params p;
    p.c1 = (float)(1.0 / range);
    p.c2 = (float)(-(double)xminf / range);
    p.maxval = (float)mv;
    p.flag = flag;
    g_par = p;
}

// ---------------------------------------------------------------- per-tile histogram + LUT (fused)
// Reverse block order: k_reduce streamed x forward, so the tail of x is
// L2-resident (L2 ~126MB vs x 128MB). First-scheduled hist blocks read the
// tail -> large L2 hit fraction. 4-deep register prefetch pipeline keeps
// MLP >= 4 regardless of atomic-op ordering conservatism.
__global__ void __launch_bounds__(256, 6) k_hist_lut(const float4* __restrict__ x) {
    __shared__ unsigned sh[8][NBINS];
    __shared__ float red[40];
    Params p = g_par;
    if (!p.flag) return;
    int t = threadIdx.x;
    int bid = (int)gridDim.x - 1 - (int)blockIdx.x;   // tile id: c*64 + gy*8 + gx
    int c = bid >> 6, gy = (bid >> 3) & 7, gx = bid & 7;
#pragma unroll
    for (int k = 0; k < 8; k++) sh[k][t] = 0u;
    __syncthreads();

    int wid = t >> 5, lane = t & 31;
    unsigned lt_mask = (1u << lane) - 1u;
    float c1 = p.c1, c2 = p.c2;
    int base = c * 262144 + (gy * 128) * 256 + gx * 32;   // float4 index of tile origin
    int g0 = base + ((t >> 5) << 8) + (t & 31);           // this thread's first float4
    // stride between iterations: 8 rows * 256 float4 = 2048

    float4 v0 = x[g0];
    float4 v1 = x[g0 + 1 * 2048];
    float4 v2 = x[g0 + 2 * 2048];
    float4 v3 = x[g0 + 3 * 2048];

#pragma unroll
    for (int it = 0; it < 16; it++) {
        float4 cur = v0; v0 = v1; v1 = v2; v2 = v3;
        if (it + 4 < 16) v3 = x[g0 + (it + 4) * 2048];
        unsigned packed = 0u;
        float vals[4] = { cur.x, cur.y, cur.z, cur.w };
#pragma unroll
        for (int j = 0; j < 4; j++) {
            float x01 = fmaf(vals[j], c1, c2);
            int hb = (int)(x01 * 256.0f);          // trunc; tiny negatives -> 0
            hb = min(max(hb, 0), 255);
            int lb = (int)(x01 * 255.0f);
            lb = min(max(lb, 0), 255);
            packed |= ((unsigned)lb) << (8 * j);
            unsigned m = __match_any_sync(0xffffffffu, hb);
            if ((m & lt_mask) == 0u)               // lowest matching lane
                atomicAdd(&sh[wid][hb], (unsigned)__popc(m));
        }
        g_bins[g0 + it * 2048] = packed;
    }
    __syncthreads();

    // counts -> clip -> redistribute -> scan -> LUT   (all exact integer f32 math)
    unsigned cnt = 0;
#pragma unroll
    for (int k = 0; k < 8; k++) cnt += sh[k][t];
    float clipped = fminf((float)cnt, p.maxval);

    float s = clipped;
#pragma unroll
    for (int o = 16; o; o >>= 1) s += __shfl_down_sync(0xffffffffu, s, o);
    if (lane == 0) red[wid] = s;
    __syncthreads();
    if (t < 32) {
        float v2s = (t < 8) ? red[t] : 0.0f;
#pragma unroll
        for (int o = 4; o; o >>= 1) v2s += __shfl_down_sync(0xffffffffu, v2s, o);
        if (t == 0) red[32] = v2s;
    }
    __syncthreads();
    float total = red[32];
    int ex = TILE_PIXELS - (int)total;     // >= 0
    int residual = ex & (NBINS - 1);
    int redist = ex >> 8;
    float hv = clipped + (float)redist + ((t < residual) ? 1.0f : 0.0f);

    // inclusive block scan
    float vsc = hv;
#pragma unroll
    for (int o = 1; o < 32; o <<= 1) {
        float u = __shfl_up_sync(0xffffffffu, vsc, o);
        if (lane >= o) vsc += u;
    }
    if (lane == 31) red[wid] = vsc;
    __syncthreads();
    float off = 0.0f;
    for (int k = 0; k < wid; k++) off += red[k];
    vsc += off;

    float lutv = floorf(fminf(vsc * (255.0f / 16384.0f), 255.0f));
    g_lut[bid * NBINS + t] = lutv;
}

// ---------------------------------------------------------------- per-region prefactored bilinear table
__global__ void __launch_bounds__(256) k_tbl() {
    Params p = g_par;
    if (!p.flag) return;
    int t = threadIdx.x, b = blockIdx.x;       // b = c*81 + ry*9 + rx
    int c = b / 81, r = b % 81;
    int ry = r / 9, rx = r % 9;
    int y0 = max(ry - 1, 0); int y1 = min(y0 + 1, 7);
    int x0 = max(rx - 1, 0); int x1 = min(x0 + 1, 7);
    const float* L = g_lut + c * 64 * NBINS;
    float l00 = L[(y0 * 8 + x0) * NBINS + t];
    float l01 = L[(y0 * 8 + x1) * NBINS + t];
    float l10 = L[(y1 * 8 + x0) * NBINS + t];
    float l11 = L[(y1 * 8 + x1) * NBINS + t];
    float4 o;
    o.x = l00;
    o.y = l01 - l00;
    o.z = l10 - l00;
    o.w = l11 - l10 - l01 + l00;
    g_tbl[b * NBINS + t] = o;
}

// ---------------------------------------------------------------- output: gather + interp + log2
// Each block handles 2048 consecutive float4s (8192 px = 8 rows) -> touches
// at most 4 region tables -> high L1 hit rate on g_tbl gathers.
__global__ void __launch_bounds__(256) k_out(const float4* __restrict__ x,
                                             float4* __restrict__ out, int n4) {
    Params p = g_par;
    int t = threadIdx.x;
    int base = blockIdx.x * 2048 + t;
    if (p.flag) {
#pragma unroll
        for (int k = 0; k < 8; k++) {
            int i = base + k * 256;
            int c   = i >> 18;
            int rem = i & 262143;
            int h   = rem >> 8;
            int w4  = (rem & 255) << 2;
            int ry  = (h + 64) >> 7;
            int rx  = (w4 + 64) >> 7;
            float wy  = fmaf((float)h,  0.0078125f, 0.50390625f - (float)ry);
            float wx0 = fmaf((float)w4, 0.0078125f, 0.50390625f - (float)rx);
            const float4* tb = g_tbl + (((c * 81) + ry * 9 + rx) << 8);
            unsigned bp = g_bins[i];
            float o[4];
#pragma unroll
            for (int j = 0; j < 4; j++) {
                float4 v = tb[(bp >> (8 * j)) & 255u];
                float wx = wx0 + (float)j * 0.0078125f;
                float itp = fmaf(wy, fmaf(wx, v.w, v.z), fmaf(wx, v.y, v.x));
                float val = itp * (1.0f / 255.0f);
                o[j] = __log2f(1.0f + val);
            }
            float4 ov; ov.x = o[0]; ov.y = o[1]; ov.z = o[2]; ov.w = o[3];
            __stcs(&out[i], ov);
        }
    } else {
#pragma unroll
        for (int k = 0; k < 8; k++) {
            int i = base + k * 256;
            if (i < n4) {
                float4 v = x[i];
                float4 ov;
                ov.x = log2f(1.0f + fmaf(v.x, p.c1, p.c2));
                ov.y = log2f(1.0f + fmaf(v.y, p.c1, p.c2));
                ov.z = log2f(1.0f + fmaf(v.z, p.c1, p.c2));
                ov.w = log2f(1.0f + fmaf(v.w, p.c1, p.c2));
                __stcs(&out[i], ov);
            }
        }
    }
}

// ---------------------------------------------------------------- launch
extern "C" void kernel_launch(void* const* d_in, const int* in_sizes, int n_in,
                              void* d_out, int out_size) {
    (void)n_in; (void)out_size;
    const float* x = (const float*)d_in[0];
    int n   = in_sizes[0];          // 32 * 1024 * 1024
    int C   = n >> 20;
    int n16 = n >> 4;
    int n4  = n >> 2;

    k_reset<<<1, 32>>>();
    k_reduce<<<1480, 256>>>((const float4*)x, n16);
    k_stats<<<1, 1>>>(n);
    k_hist_lut<<<C * 64, 256>>>((const float4*)x);
    k_tbl<<<C * 81, 256>>>();
    k_out<<<n4 / 2048, 256>>>((const float4*)x, (float4*)d_out, n4);
}

// round 3
// speedup vs baseline: 1.3224x; 1.1672x over previous
#include <cuda_runtime.h>
#include <cstdint>
#include <math.h>

#define NBINS 256
#define TILE_PIXELS 16384   // 128*128
#define MAXC 32

struct Params { float c1, c2, maxval; int flag; int hot; };

__device__ double   g_sum_d;
__device__ double   g_sumsq_d;
__device__ unsigned g_min_enc;
__device__ unsigned g_max_enc;
__device__ Params   g_par;
__device__ float    g_lut[MAXC * 64 * NBINS];          // 2 MB
__device__ float4   g_tbl[MAXC * 81 * NBINS];          // 10.6 MB  (p,q,r,s) per region/bin
__device__ unsigned g_bins[(MAXC << 20) >> 2];         // 32 MB packed u8 lookup bins

__device__ __forceinline__ unsigned fenc(float f) {
    unsigned u = __float_as_uint(f);
    return (u & 0x80000000u) ? ~u : (u | 0x80000000u);
}
__device__ __forceinline__ float fdec(unsigned e) {
    unsigned u = (e & 0x80000000u) ? (e & 0x7FFFFFFFu) : ~e;
    return __uint_as_float(u);
}

// ---------------------------------------------------------------- reset
__global__ void k_reset() {
    if (threadIdx.x == 0) {
        g_sum_d = 0.0; g_sumsq_d = 0.0;
        g_min_enc = 0xFFFFFFFFu; g_max_enc = 0u;
    }
}

// ---------------------------------------------------------------- reduce: sum, sumsq, min, max
__global__ void __launch_bounds__(256) k_reduce(const float4* __restrict__ x, int n16) {
    double s = 0.0, q = 0.0;
    float mn = 3.4e38f, mx = -3.4e38f;
    int stride = gridDim.x * blockDim.x;
    for (int i = blockIdx.x * blockDim.x + threadIdx.x; i < n16; i += stride) {
        const float4* p = x + (size_t)i * 4;
        float fs = 0.0f, fq = 0.0f;
#pragma unroll
        for (int g = 0; g < 4; g++) {
            float4 v = p[g];
            fs += v.x; fq = fmaf(v.x, v.x, fq); mn = fminf(mn, v.x); mx = fmaxf(mx, v.x);
            fs += v.y; fq = fmaf(v.y, v.y, fq); mn = fminf(mn, v.y); mx = fmaxf(mx, v.y);
            fs += v.z; fq = fmaf(v.z, v.z, fq); mn = fminf(mn, v.z); mx = fmaxf(mx, v.z);
            fs += v.w; fq = fmaf(v.w, v.w, fq); mn = fminf(mn, v.w); mx = fmaxf(mx, v.w);
        }
        s += (double)fs; q += (double)fq;
    }
#pragma unroll
    for (int o = 16; o; o >>= 1) {
        s  += __shfl_down_sync(0xffffffffu, s, o);
        q  += __shfl_down_sync(0xffffffffu, q, o);
        mn = fminf(mn, __shfl_down_sync(0xffffffffu, mn, o));
        mx = fmaxf(mx, __shfl_down_sync(0xffffffffu, mx, o));
    }
    __shared__ double ss[8], sq[8];
    __shared__ float  smn[8], smx[8];
    int w = threadIdx.x >> 5, l = threadIdx.x & 31;
    if (l == 0) { ss[w] = s; sq[w] = q; smn[w] = mn; smx[w] = mx; }
    __syncthreads();
    if (w == 0) {
        s  = (l < 8) ? ss[l]  : 0.0;
        q  = (l < 8) ? sq[l]  : 0.0;
        mn = (l < 8) ? smn[l] : 3.4e38f;
        mx = (l < 8) ? smx[l] : -3.4e38f;
#pragma unroll
        for (int o = 4; o; o >>= 1) {
            s  += __shfl_down_sync(0xffffffffu, s, o);
            q  += __shfl_down_sync(0xffffffffu, q, o);
            mn = fminf(mn, __shfl_down_sync(0xffffffffu, mn, o));
            mx = fmaxf(mx, __shfl_down_sync(0xffffffffu, mx, o));
        }
        if (l == 0) {
            atomicAdd(&g_sum_d, s);
            atomicAdd(&g_sumsq_d, q);
            atomicMin(&g_min_enc, fenc(mn));
            atomicMax(&g_max_enc, fenc(mx));
        }
    }
}

// ---------------------------------------------------------------- scalar stats
__global__ void k_stats(int n) {
    double s = g_sum_d, q = g_sumsq_d;
    double dn = (double)n;
    double var = (q - s * s / dn) / (dn - 1.0);
    double sd = sqrt(var);
    float xminf = fdec(g_min_enc), xmaxf = fdec(g_max_enc);
    double range = (double)xmaxf - (double)xminf;
    double ct = sd / range;                 // std(x01) == std(x)/range
    int flag = (ct < 0.05) ? 1 : 0;
    double beta = 10.0 * ct;
    double cl = 1.0 / (1.0 - beta) + beta;
    double mv = floor(cl * (double)TILE_PIXELS / (double)NBINS);
    if (mv < 1.0) mv = 1.0;
    Params p;
    p.c1 = (float)(1.0 / range);
    p.c2 = (float)(-(double)xminf / range);
    p.maxval = (float)mv;
    p.flag = flag;
    // heuristic hot bin = bin containing x=0 (mode); correctness does not depend on it
    int hot = (int)(p.c2 * 256.0f);
    hot = hot < 0 ? 0 : (hot > 255 ? 255 : hot);
    p.hot = hot;
    g_par = p;
}

// ---------------------------------------------------------------- per-tile histogram + LUT (fused)
// Per-thread private u8 histograms in 64KB dynamic smem (no atomics, no races:
// slot (bin,t) = bin*256 + ((t + 4*bin) & 255) is unique per thread and swizzled
// across banks). Hot bin (bin of x=0) counted in a register. dp4a row reduce.
extern __shared__ unsigned char sh8[];
__global__ void __launch_bounds__(256) k_hist_lut(const float4* __restrict__ x) {
    __shared__ float red[40];
    Params p = g_par;
    if (!p.flag) return;
    int t = threadIdx.x;
    int bid = (int)gridDim.x - 1 - (int)blockIdx.x;   // tile id: c*64 + gy*8 + gx
    int c = bid >> 6, gy = (bid >> 3) & 7, gx = bid & 7;

    // zero 64KB: 4096 uint4 / 256 threads = 16 each
    uint4* z = (uint4*)sh8;
    uint4 zz; zz.x = 0u; zz.y = 0u; zz.z = 0u; zz.w = 0u;
#pragma unroll
    for (int k = 0; k < 16; k++) z[k * 256 + t] = zz;
    __syncthreads();

    int wid = t >> 5, lane = t & 31;
    float c1 = p.c1, c2 = p.c2;
    int hot = p.hot;
    int base = c * 262144 + (gy * 128) * 256 + gx * 32;   // float4 index of tile origin
    int g0 = base + ((t >> 5) << 8) + (t & 31);           // this thread's first float4
    int hotcnt = 0;

    float4 v0 = x[g0];
    float4 v1 = x[g0 + 1 * 2048];
    float4 v2 = x[g0 + 2 * 2048];
    float4 v3 = x[g0 + 3 * 2048];

#pragma unroll
    for (int it = 0; it < 16; it++) {
        float4 cur = v0; v0 = v1; v1 = v2; v2 = v3;
        if (it + 4 < 16) v3 = x[g0 + (it + 4) * 2048];
        unsigned packed = 0u;
        float vals[4] = { cur.x, cur.y, cur.z, cur.w };
#pragma unroll
        for (int j = 0; j < 4; j++) {
            float x01 = fmaf(vals[j], c1, c2);
            int hb = (int)(x01 * 256.0f);          // trunc; tiny negatives -> 0
            hb = min(max(hb, 0), 255);
            int lb = (int)(x01 * 255.0f);
            lb = min(max(lb, 0), 255);
            packed |= ((unsigned)lb) << (8 * j);
            if (hb == hot) {
                hotcnt++;
            } else {
                int slot = (hb << 8) | ((t + (hb << 2)) & 255);
                sh8[slot]++;                      // private: no race
            }
        }
        g_bins[g0 + it * 2048] = packed;
    }
    // hot-bin slot was never touched by the RMW path -> plain store
    sh8[(hot << 8) | ((t + (hot << 2)) & 255)] = (unsigned char)hotcnt;
    __syncthreads();

    // reduce row t (256 u8 = 64 u32), lane-staggered to avoid bank conflicts
    const unsigned* row = (const unsigned*)sh8 + (t << 6);
    unsigned cnt = 0;
#pragma unroll
    for (int ii = 0; ii < 64; ii++) {
        unsigned wv = row[(lane + ii) & 63];
        cnt = __dp4a(wv, 0x01010101u, cnt);
    }

    // counts -> clip -> redistribute -> scan -> LUT   (all exact integer f32 math)
    float clipped = fminf((float)cnt, p.maxval);

    float s = clipped;
#pragma unroll
    for (int o = 16; o; o >>= 1) s += __shfl_down_sync(0xffffffffu, s, o);
    if (lane == 0) red[wid] = s;
    __syncthreads();
    if (t < 32) {
        float v2s = (t < 8) ? red[t] : 0.0f;
#pragma unroll
        for (int o = 4; o; o >>= 1) v2s += __shfl_down_sync(0xffffffffu, v2s, o);
        if (t == 0) red[32] = v2s;
    }
    __syncthreads();
    float total = red[32];
    int ex = TILE_PIXELS - (int)total;     // >= 0
    int residual = ex & (NBINS - 1);
    int redist = ex >> 8;
    float hv = clipped + (float)redist + ((t < residual) ? 1.0f : 0.0f);

    // inclusive block scan
    float vsc = hv;
#pragma unroll
    for (int o = 1; o < 32; o <<= 1) {
        float u = __shfl_up_sync(0xffffffffu, vsc, o);
        if (lane >= o) vsc += u;
    }
    if (lane == 31) red[wid] = vsc;
    __syncthreads();
    float off = 0.0f;
    for (int k = 0; k < wid; k++) off += red[k];
    vsc += off;

    float lutv = floorf(fminf(vsc * (255.0f / 16384.0f), 255.0f));
    g_lut[bid * NBINS + t] = lutv;
}

// ---------------------------------------------------------------- per-region prefactored bilinear table
__global__ void __launch_bounds__(256) k_tbl() {
    Params p = g_par;
    if (!p.flag) return;
    int t = threadIdx.x, b = blockIdx.x;       // b = c*81 + ry*9 + rx
    int c = b / 81, r = b % 81;
    int ry = r / 9, rx = r % 9;
    int y0 = max(ry - 1, 0); int y1 = min(y0 + 1, 7);
    int x0 = max(rx - 1, 0); int x1 = min(x0 + 1, 7);
    const float* L = g_lut + c * 64 * NBINS;
    float l00 = L[(y0 * 8 + x0) * NBINS + t];
    float l01 = L[(y0 * 8 + x1) * NBINS + t];
    float l10 = L[(y1 * 8 + x0) * NBINS + t];
    float l11 = L[(y1 * 8 + x1) * NBINS + t];
    float4 o;
    o.x = l00;
    o.y = l01 - l00;
    o.z = l10 - l00;
    o.w = l11 - l10 - l01 + l00;
    g_tbl[b * NBINS + t] = o;
}

// ---------------------------------------------------------------- output: gather + interp + log2
__global__ void __launch_bounds__(256) k_out(const float4* __restrict__ x,
                                             float4* __restrict__ out, int n4) {
    Params p = g_par;
    int t = threadIdx.x;
    int base = blockIdx.x * 2048 + t;
    if (p.flag) {
#pragma unroll
        for (int k = 0; k < 8; k++) {
            int i = base + k * 256;
            int c   = i >> 18;
            int rem = i & 262143;
            int h   = rem >> 8;
            int w4  = (rem & 255) << 2;
            int ry  = (h + 64) >> 7;
            int rx  = (w4 + 64) >> 7;
            float wy  = fmaf((float)h,  0.0078125f, 0.50390625f - (float)ry);
            float wx0 = fmaf((float)w4, 0.0078125f, 0.50390625f - (float)rx);
            const float4* tb = g_tbl + (((c * 81) + ry * 9 + rx) << 8);
            unsigned bp = g_bins[i];
            float o[4];
#pragma unroll
            for (int j = 0; j < 4; j++) {
                float4 v = tb[(bp >> (8 * j)) & 255u];
                float wx = wx0 + (float)j * 0.0078125f;
                float itp = fmaf(wy, fmaf(wx, v.w, v.z), fmaf(wx, v.y, v.x));
                float val = itp * (1.0f / 255.0f);
                o[j] = __log2f(1.0f + val);
            }
            float4 ov; ov.x = o[0]; ov.y = o[1]; ov.z = o[2]; ov.w = o[3];
            __stcs(&out[i], ov);
        }
    } else {
#pragma unroll
        for (int k = 0; k < 8; k++) {
            int i = base + k * 256;
            if (i < n4) {
                float4 v = x[i];
                float4 ov;
                ov.x = log2f(1.0f + fmaf(v.x, p.c1, p.c2));
                ov.y = log2f(1.0f + fmaf(v.y, p.c1, p.c2));
                ov.z = log2f(1.0f + fmaf(v.z, p.c1, p.c2));
                ov.w = log2f(1.0f + fmaf(v.w, p.c1, p.c2));
                __stcs(&out[i], ov);
            }
        }
    }
}

// ---------------------------------------------------------------- launch
extern "C" void kernel_launch(void* const* d_in, const int* in_sizes, int n_in,
                              void* d_out, int out_size) {
    (void)n_in; (void)out_size;
    const float* x = (const float*)d_in[0];
    int n   = in_sizes[0];          // 32 * 1024 * 1024
    int C   = n >> 20;
    int n16 = n >> 4;
    int n4  = n >> 2;

    static int smem_set = 0;
    if (!smem_set) {
        cudaFuncSetAttribute(k_hist_lut, cudaFuncAttributeMaxDynamicSharedMemorySize, 65536);
        smem_set = 1;
    }

    k_reset<<<1, 32>>>();
    k_reduce<<<1480, 256>>>((const float4*)x, n16);
    k_stats<<<1, 1>>>(n);
    k_hist_lut<<<C * 64, 256, 65536>>>((const float4*)x);
    k_tbl<<<C * 81, 256>>>();
    k_out<<<n4 / 2048, 256>>>((const float4*)x, (float4*)d_out, n4);
}